// round 8
// baseline (speedup 1.0000x reference)
#include <cuda_runtime.h>
#include <cuda_bf16.h>
#include <cstdint>
#include <math.h>

#define BATCH 4
#define CCH   128
#define NSP   4096

// Q scale = C^-0.5 * log2(e)  (exp(S) computed as exp2(S'))
#define QSCALE 0.12751743f

// Scratch (device globals; no allocation allowed)
__device__ __nv_bfloat16 g_q[BATCH*CCH*NSP];   // [b][c][n], pre-scaled
__device__ __nv_bfloat16 g_k[BATCH*NSP*CCH];   // [b][n][c]
__device__ __nv_bfloat16 g_v[BATCH*CCH*NSP];   // [b][c][n]
__device__ __nv_bfloat16 g_o[BATCH*NSP*CCH];   // [b][n][c] attn out
__device__ float2        g_part[256];          // GN partial sums
__device__ float         g_cA[BATCH*CCH];      // per-(b,c) affine scale
__device__ float         g_cB[BATCH*CCH];      // per-(b,c) affine offset

extern __shared__ char dynsm[];

// ---------------------------------------------------------------------------
// Baseline-PTX helpers
// ---------------------------------------------------------------------------
__device__ __forceinline__ uint32_t smem_u32(const void* p) {
    uint32_t a;
    asm("{ .reg .u64 t; cvta.to.shared.u64 t, %1; cvt.u32.u64 %0, t; }"
        : "=r"(a) : "l"(p));
    return a;
}

#define LDSM4(R, addr) \
    asm volatile("ldmatrix.sync.aligned.m8n8.x4.shared.b16 {%0,%1,%2,%3}, [%4];" \
        : "=r"((R)[0]), "=r"((R)[1]), "=r"((R)[2]), "=r"((R)[3]) : "r"(addr))

#define LDSM4T(R, addr) \
    asm volatile("ldmatrix.sync.aligned.m8n8.x4.trans.shared.b16 {%0,%1,%2,%3}, [%4];" \
        : "=r"((R)[0]), "=r"((R)[1]), "=r"((R)[2]), "=r"((R)[3]) : "r"(addr))

__device__ __forceinline__ void mma16816(float* d, const uint32_t* a, const uint32_t* b) {
    asm volatile(
        "mma.sync.aligned.m16n8k16.row.col.f32.bf16.bf16.f32 "
        "{%0,%1,%2,%3}, {%4,%5,%6,%7}, {%8,%9}, {%0,%1,%2,%3};"
        : "+f"(d[0]), "+f"(d[1]), "+f"(d[2]), "+f"(d[3])
        : "r"(a[0]), "r"(a[1]), "r"(a[2]), "r"(a[3]), "r"(b[0]), "r"(b[1]));
}

__device__ __forceinline__ void cp16(uint32_t dst, const void* src) {
    asm volatile("cp.async.cg.shared.global [%0], [%1], 16;"
                 :: "r"(dst), "l"(__cvta_generic_to_global(src)));
}
#define CP_COMMIT() asm volatile("cp.async.commit_group;" ::: "memory")
#define CP_WAIT(n)  asm volatile("cp.async.wait_group %0;" :: "n"(n) : "memory")

__device__ __forceinline__ uint32_t packbf(float lo, float hi) {
    __nv_bfloat162 h = __float22bfloat162_rn(make_float2(lo, hi));
    return *reinterpret_cast<uint32_t*>(&h);
}

__device__ __forceinline__ float ex2f(float x) {
    float r;
    asm("ex2.approx.f32 %0, %1;" : "=f"(r) : "f"(x));
    return r;
}

// ---------------------------------------------------------------------------
// GN stats pass 1: 256 blocks, each sums an 8192-float slice of x
// ---------------------------------------------------------------------------
__global__ void __launch_bounds__(256) gn_part_k(const float* __restrict__ x,
                                                 float2* __restrict__ part) {
    const float4* p = (const float4*)(x + (size_t)blockIdx.x * 8192);
    float s = 0.f, s2 = 0.f;
    for (int e = threadIdx.x; e < 2048; e += 256) {
        float4 v = p[e];
        s  += v.x + v.y + v.z + v.w;
        s2 += v.x*v.x + v.y*v.y + v.z*v.z + v.w*v.w;
    }
    __shared__ float r1[256], r2[256];
    r1[threadIdx.x] = s; r2[threadIdx.x] = s2;
    __syncthreads();
    for (int off = 128; off > 0; off >>= 1) {
        if (threadIdx.x < off) {
            r1[threadIdx.x] += r1[threadIdx.x + off];
            r2[threadIdx.x] += r2[threadIdx.x + off];
        }
        __syncthreads();
    }
    if (threadIdx.x == 0) part[blockIdx.x] = make_float2(r1[0], r2[0]);
}

// GN stats pass 2: 1 block, 512 threads = (b, c); per-(b,c) affine
__global__ void __launch_bounds__(512) gn_fin_k(const float* __restrict__ gs,
                                                const float* __restrict__ gb,
                                                const float2* __restrict__ part,
                                                float* __restrict__ cA,
                                                float* __restrict__ cB) {
    int t = threadIdx.x;
    int b = t >> 7, c = t & 127, g = c >> 4;
    float s = 0.f, s2 = 0.f;
#pragma unroll
    for (int i = 0; i < 8; i++) {
        float2 v = part[b * 64 + g * 8 + i];
        s += v.x; s2 += v.y;
    }
    const float inv_n = 1.f / 65536.f;
    float mean = s * inv_n;
    float var  = s2 * inv_n - mean * mean;
    float rstd = rsqrtf(var + 1e-6f);
    float a = rstd * gs[c];
    cA[t] = a;
    cB[t] = gb[c] - mean * a;
}

// ---------------------------------------------------------------------------
// Fused QKV GEMM (tensor cores). grid (32, B), 256 thr.
// Outputs: Q [b][c][n] (pre-scaled), K [b][n][c] (scatter), V [b][c][n].
// ---------------------------------------------------------------------------
#define WP3 272
#define QKV_SM_X   104448                 // 3 * 34816
#define QKV_SMEM   (104448 + 34816)       // 139264

__global__ void __launch_bounds__(256, 1) qkv_kernel(
        const float* __restrict__ x,
        const float* __restrict__ cA, const float* __restrict__ cB,
        const float* __restrict__ wq, const float* __restrict__ bq,
        const float* __restrict__ wk, const float* __restrict__ bk,
        const float* __restrict__ wv, const float* __restrict__ bv,
        __nv_bfloat16* __restrict__ Q, __nv_bfloat16* __restrict__ K,
        __nv_bfloat16* __restrict__ V) {
    const int tid = threadIdx.x, lane = tid & 31, w = tid >> 5;
    const int b = blockIdx.y, n0 = blockIdx.x * 128;

    // stage weights f32 -> bf16 smem [m][k], pitch 272
    const float* Wsrc[3] = {wq, wk, wv};
#pragma unroll
    for (int o = 0; o < 3; o++) {
        const float4* wp4 = (const float4*)Wsrc[o];
        char* dst = dynsm + o * 34816;
        for (int e = tid; e < 4096; e += 256) {
            int m = e >> 5, k4 = e & 31;
            float4 v = wp4[e];
            uint2 pk;
            pk.x = packbf(v.x, v.y); pk.y = packbf(v.z, v.w);
            *(uint2*)(dst + m * WP3 + k4 * 8) = pk;
        }
    }
    // stage x tile [c][n] with GN affine -> bf16 smem pitch 272
    {
        char* dst = dynsm + QKV_SM_X;
        for (int e = tid; e < 4096; e += 256) {
            int c = e >> 5, n4 = e & 31;
            float4 v = *(const float4*)(x + ((size_t)b * CCH + c) * NSP + n0 + n4 * 4);
            float a = cA[b * CCH + c], bb = cB[b * CCH + c];
            v.x = fmaf(v.x, a, bb); v.y = fmaf(v.y, a, bb);
            v.z = fmaf(v.z, a, bb); v.w = fmaf(v.w, a, bb);
            uint2 pk;
            pk.x = packbf(v.x, v.y); pk.y = packbf(v.z, v.w);
            *(uint2*)(dst + c * WP3 + n4 * 8) = pk;
        }
    }
    __syncthreads();

    const uint32_t smb = smem_u32(dynsm);
    const int g = lane >> 2, q4 = lane & 3;
    const uint32_t a_lane = (uint32_t)((16 * w + (lane & 15)) * WP3 + (lane >> 4) * 16);
    const uint32_t b_base = smb + QKV_SM_X + (lane & 15) * WP3 + (lane >> 4) * 16;

#pragma unroll
    for (int o = 0; o < 3; o++) {
        uint32_t af[8][4];
        const uint32_t a_base = smb + o * 34816 + a_lane;
#pragma unroll
        for (int kk = 0; kk < 8; kk++) LDSM4(af[kk], a_base + kk * 32);

        float acc[16][4];
#pragma unroll
        for (int i = 0; i < 16; i++)
#pragma unroll
            for (int j = 0; j < 4; j++) acc[i][j] = 0.f;

#pragma unroll
        for (int nbp = 0; nbp < 8; nbp++) {
#pragma unroll
            for (int kk = 0; kk < 8; kk++) {
                uint32_t bb[4];
                LDSM4T(bb, b_base + nbp * 32 + kk * (16 * WP3));
                mma16816(acc[2 * nbp],     af[kk], bb);
                mma16816(acc[2 * nbp + 1], af[kk], bb + 2);
            }
        }

        const int m = 16 * w + g;
        if (o == 0) {
            const float bi0 = bq[m], bi1 = bq[m + 8];
            __nv_bfloat16* op = Q + (size_t)b * CCH * NSP;
#pragma unroll
            for (int nb = 0; nb < 16; nb++) {
                int n = n0 + 8 * nb + 2 * q4;
                *(uint32_t*)&op[(size_t)m * NSP + n] =
                    packbf((acc[nb][0] + bi0) * QSCALE, (acc[nb][1] + bi0) * QSCALE);
                *(uint32_t*)&op[(size_t)(m + 8) * NSP + n] =
                    packbf((acc[nb][2] + bi1) * QSCALE, (acc[nb][3] + bi1) * QSCALE);
            }
        } else if (o == 1) {
            // K -> [b][n][c] scatter (u16 stores)
            const float bi0 = bk[m], bi1 = bk[m + 8];
            __nv_bfloat16* op = K + (size_t)b * NSP * CCH;
#pragma unroll
            for (int nb = 0; nb < 16; nb++) {
                int n = n0 + 8 * nb + 2 * q4;
                op[(size_t)n * CCH + m]           = __float2bfloat16_rn(acc[nb][0] + bi0);
                op[(size_t)(n + 1) * CCH + m]     = __float2bfloat16_rn(acc[nb][1] + bi0);
                op[(size_t)n * CCH + m + 8]       = __float2bfloat16_rn(acc[nb][2] + bi1);
                op[(size_t)(n + 1) * CCH + m + 8] = __float2bfloat16_rn(acc[nb][3] + bi1);
            }
        } else {
            const float bi0 = bv[m], bi1 = bv[m + 8];
            __nv_bfloat16* op = V + (size_t)b * CCH * NSP;
#pragma unroll
            for (int nb = 0; nb < 16; nb++) {
                int n = n0 + 8 * nb + 2 * q4;
                *(uint32_t*)&op[(size_t)m * NSP + n] =
                    packbf(acc[nb][0] + bi0, acc[nb][1] + bi0);
                *(uint32_t*)&op[(size_t)(m + 8) * NSP + n] =
                    packbf(acc[nb][2] + bi1, acc[nb][3] + bi1);
            }
        }
    }
}

// ---------------------------------------------------------------------------
// Flash attention (bf16 mma.sync). grid (32, B), 256 thr (8 warps).
// Q [b][c][n] (trans-loaded ONCE), K [b][n][c] -> smem [key][c] (non-trans B),
// V [b][c][n] -> smem [c][key] (non-trans B). exp2 via ex2; O out bf16 [b][n][c].
// ---------------------------------------------------------------------------
#define AQP 272
#define AKP 272                               // K tile [64 keys][128c] pitch
#define AVP 144                               // V tile [128c][64 keys] pitch
#define AKBUF (64 * AKP)                      // 17408
#define AVBUF (128 * AVP)                     // 18432
#define ASM_Q 0
#define ASM_K 34816
#define ASM_V (ASM_K + 2 * AKBUF)             // 69632
#define ATTN_SMEM (ASM_V + 2 * AVBUF)         // 106496

__global__ void __launch_bounds__(256, 1) attn_kernel(
        const __nv_bfloat16* __restrict__ Q,
        const __nv_bfloat16* __restrict__ K,
        const __nv_bfloat16* __restrict__ V,
        __nv_bfloat16* __restrict__ O) {
    const uint32_t smb = smem_u32(dynsm);
    const int tid = threadIdx.x, lane = tid & 31, w = tid >> 5;
    const int b = blockIdx.y, n0 = blockIdx.x * 128;

    const __nv_bfloat16* qg = Q + (size_t)b * CCH * NSP;
    const __nv_bfloat16* kg = K + (size_t)b * NSP * CCH;
    const __nv_bfloat16* vg = V + (size_t)b * CCH * NSP;

    // Q tile [c=128][i=128]: 2048 x 16B
#pragma unroll
    for (int i = 0; i < 8; i++) {
        int id = tid + 256 * i;
        int c = id >> 4, ch = id & 15;
        cp16(smb + ASM_Q + c * AQP + ch * 16, qg + (size_t)c * NSP + n0 + ch * 8);
    }
    CP_COMMIT();
    // KV tile 0: K [key][c] rows, V [c][key]
#pragma unroll
    for (int i = 0; i < 4; i++) {
        int id = tid + 256 * i;
        int r = id >> 4, ch = id & 15;
        cp16(smb + ASM_K + r * AKP + ch * 16, kg + (size_t)r * CCH + ch * 8);
    }
#pragma unroll
    for (int i = 0; i < 4; i++) {
        int id = tid + 256 * i;
        int c = id >> 3, ch = id & 7;
        cp16(smb + ASM_V + c * AVP + ch * 16, vg + (size_t)c * NSP + ch * 8);
    }
    CP_COMMIT();

    const int g = lane >> 2, q4 = lane & 3;
    // non-trans B-frag addressing (K and V)
    const uint32_t rowsel = (uint32_t)((lane & 7) + ((lane >> 4) << 3));
    const uint32_t hi16   = (uint32_t)(((lane >> 3) & 1) * 16);

    float oacc[16][4];
#pragma unroll
    for (int u = 0; u < 16; u++)
#pragma unroll
        for (int i = 0; i < 4; i++) oacc[u][i] = 0.f;
    float s_lo = 0.f, s_hi = 0.f;

    uint32_t qf[8][4];

    for (int t = 0; t < 64; t++) {
        if (t < 63) {
            const int m0 = (t + 1) * 64, bsel = (t + 1) & 1;
#pragma unroll
            for (int i = 0; i < 4; i++) {
                int id = tid + 256 * i;
                int r = id >> 4, ch = id & 15;
                cp16(smb + ASM_K + bsel * AKBUF + r * AKP + ch * 16,
                     kg + (size_t)(m0 + r) * CCH + ch * 8);
            }
#pragma unroll
            for (int i = 0; i < 4; i++) {
                int id = tid + 256 * i;
                int c = id >> 3, ch = id & 7;
                cp16(smb + ASM_V + bsel * AVBUF + c * AVP + ch * 16,
                     vg + (size_t)c * NSP + m0 + ch * 8);
            }
            CP_COMMIT();
            CP_WAIT(1);
        } else {
            CP_WAIT(0);
        }
        __syncthreads();

        if (t == 0) {
            // hoist Q fragments (trans) once: rows=queries from [c][q] tile
            const uint32_t arow = (uint32_t)((lane & 7) + ((lane >> 4) << 3));
            const uint32_t ahi  = (uint32_t)(((lane >> 3) & 1) * 16);
            const uint32_t qaddr = smb + ASM_Q + arow * AQP + 32 * w + ahi;
#pragma unroll
            for (int kk = 0; kk < 8; kk++) LDSM4T(qf[kk], qaddr + kk * (16 * AQP));
        }

        const uint32_t kb = smb + ASM_K + (t & 1) * AKBUF + rowsel * AKP + hi16;
        const uint32_t vb = smb + ASM_V + (t & 1) * AVBUF + rowsel * AVP + hi16;

        // ---- S[16 x 64] = Q · Kᵀ (B non-trans from [key][c] rows)
        float sacc[8][4];
#pragma unroll
        for (int j = 0; j < 8; j++)
#pragma unroll
            for (int i = 0; i < 4; i++) sacc[j][i] = 0.f;

#pragma unroll
        for (int kk = 0; kk < 8; kk++) {
#pragma unroll
            for (int jp = 0; jp < 4; jp++) {
                uint32_t bb[4];
                LDSM4(bb, kb + jp * (16 * AKP) + kk * 32);
                mma16816(sacc[2 * jp],     qf[kk], bb);
                mma16816(sacc[2 * jp + 1], qf[kk], bb + 2);
            }
        }

        // ---- P = exp2(S'); frags reused directly as A
        uint32_t pa[8][2];
#pragma unroll
        for (int j = 0; j < 8; j++) {
            float p0 = ex2f(sacc[j][0]);
            float p1 = ex2f(sacc[j][1]);
            float p2 = ex2f(sacc[j][2]);
            float p3 = ex2f(sacc[j][3]);
            s_lo += p0 + p1;
            s_hi += p2 + p3;
            pa[j][0] = packbf(p0, p1);
            pa[j][1] = packbf(p2, p3);
        }

        // ---- O[16 x 128] += P · Vᵀ
#pragma unroll
        for (int kk = 0; kk < 4; kk++) {
            uint32_t a[4] = { pa[2 * kk][0], pa[2 * kk][1],
                              pa[2 * kk + 1][0], pa[2 * kk + 1][1] };
#pragma unroll
            for (int u = 0; u < 8; u++) {
                uint32_t bb[4];
                LDSM4(bb, vb + u * (16 * AVP) + kk * 32);
                mma16816(oacc[2 * u],     a, bb);
                mma16816(oacc[2 * u + 1], a, bb + 2);
            }
        }
        __syncthreads();
    }

    s_lo += __shfl_xor_sync(0xFFFFFFFFu, s_lo, 1);
    s_lo += __shfl_xor_sync(0xFFFFFFFFu, s_lo, 2);
    s_hi += __shfl_xor_sync(0xFFFFFFFFu, s_hi, 1);
    s_hi += __shfl_xor_sync(0xFFFFFFFFu, s_hi, 2);
    const float inv_lo = 1.f / s_lo;
    const float inv_hi = 1.f / s_hi;

    __nv_bfloat16* op = O + ((size_t)b * NSP + n0 + 16 * w) * CCH;
#pragma unroll
    for (int u = 0; u < 16; u++) {
        int c = 8 * u + 2 * q4;
        *(uint32_t*)&op[(size_t)g * CCH + c] =
            packbf(oacc[u][0] * inv_lo, oacc[u][1] * inv_lo);
        *(uint32_t*)&op[(size_t)(g + 8) * CCH + c] =
            packbf(oacc[u][2] * inv_hi, oacc[u][3] * inv_hi);
    }
}

// ---------------------------------------------------------------------------
// Proj GEMM (tensor cores) + residual. grid (32, B), 256 thr.
// ---------------------------------------------------------------------------
#define PROJ_SM_O  34816
#define PROJ_SMEM  (34816 * 2)

__global__ void __launch_bounds__(256, 1) proj_kernel(
        const float* __restrict__ wp, const float* __restrict__ bp,
        const __nv_bfloat16* __restrict__ Oin,
        const float* __restrict__ x, float* __restrict__ out) {
    const int tid = threadIdx.x, lane = tid & 31, w = tid >> 5;
    const int b = blockIdx.y, n0 = blockIdx.x * 128;
    const uint32_t smb = smem_u32(dynsm);

    const __nv_bfloat16* og = Oin + ((size_t)b * NSP + n0) * CCH;
#pragma unroll
    for (int i = 0; i < 8; i++) {
        int id = tid + 256 * i;
        int n = id >> 4, ch = id & 15;
        cp16(smb + PROJ_SM_O + n * WP3 + ch * 16, og + (size_t)n * CCH + ch * 8);
    }
    CP_COMMIT();

    {
        const float4* wp4 = (const float4*)wp;
        for (int e = tid; e < 4096; e += 256) {
            int m = e >> 5, k4 = e & 31;
            float4 v = wp4[e];
            uint2 pk;
            pk.x = packbf(v.x, v.y); pk.y = packbf(v.z, v.w);
            *(uint2*)(dynsm + m * WP3 + k4 * 8) = pk;
        }
    }
    CP_WAIT(0);
    __syncthreads();

    const int g = lane >> 2, q4 = lane & 3;
    const uint32_t rowsel = (uint32_t)((lane & 7) + ((lane >> 4) << 3));
    const uint32_t hi16   = (uint32_t)(((lane >> 3) & 1) * 16);

    uint32_t af[8][4];
    const uint32_t a_base = smb + (16 * w + (lane & 15)) * WP3 + (lane >> 4) * 16;
#pragma unroll
    for (int kk = 0; kk < 8; kk++) LDSM4(af[kk], a_base + kk * 32);

    float acc[16][4];
#pragma unroll
    for (int i = 0; i < 16; i++)
#pragma unroll
        for (int j = 0; j < 4; j++) acc[i][j] = 0.f;

    const uint32_t b_base = smb + PROJ_SM_O + rowsel * WP3 + hi16;
#pragma unroll
    for (int nbp = 0; nbp < 8; nbp++) {
#pragma unroll
        for (int kk = 0; kk < 8; kk++) {
            uint32_t bb[4];
            LDSM4(bb, b_base + nbp * (16 * WP3) + kk * 32);
            mma16816(acc[2 * nbp],     af[kk], bb);
            mma16816(acc[2 * nbp + 1], af[kk], bb + 2);
        }
    }

    const int m = 16 * w + g;
    const float bi0 = bp[m], bi1 = bp[m + 8];
    const float* xr0 = x + ((size_t)b * CCH + m) * NSP;
    const float* xr1 = x + ((size_t)b * CCH + m + 8) * NSP;
    float* o0 = out + ((size_t)b * CCH + m) * NSP;
    float* o1 = out + ((size_t)b * CCH + m + 8) * NSP;
#pragma unroll
    for (int nb = 0; nb < 16; nb++) {
        int n = n0 + 8 * nb + 2 * q4;
        float2 r0 = *(const float2*)(xr0 + n);
        float2 r1 = *(const float2*)(xr1 + n);
        float2 v0 = make_float2(acc[nb][0] + bi0 + r0.x, acc[nb][1] + bi0 + r0.y);
        float2 v1 = make_float2(acc[nb][2] + bi1 + r1.x, acc[nb][3] + bi1 + r1.y);
        *(float2*)(o0 + n) = v0;
        *(float2*)(o1 + n) = v1;
    }
}

// ---------------------------------------------------------------------------
extern "C" void kernel_launch(void* const* d_in, const int* in_sizes, int n_in,
                              void* d_out, int out_size) {
    const float* x  = (const float*)d_in[0];
    const float* gs = (const float*)d_in[1];
    const float* gb = (const float*)d_in[2];
    const float* wq = (const float*)d_in[3];
    const float* bq = (const float*)d_in[4];
    const float* wk = (const float*)d_in[5];
    const float* bk = (const float*)d_in[6];
    const float* wv = (const float*)d_in[7];
    const float* bv = (const float*)d_in[8];
    const float* wp = (const float*)d_in[9];
    const float* bp = (const float*)d_in[10];
    float* out = (float*)d_out;

    static __nv_bfloat16 *qP=nullptr, *kP=nullptr, *vP=nullptr, *oP=nullptr;
    static float2* partP = nullptr;
    static float *cAP = nullptr, *cBP = nullptr;
    static bool init = false;
    if (!init) {
        cudaGetSymbolAddress((void**)&qP, g_q);
        cudaGetSymbolAddress((void**)&kP, g_k);
        cudaGetSymbolAddress((void**)&vP, g_v);
        cudaGetSymbolAddress((void**)&oP, g_o);
        cudaGetSymbolAddress((void**)&partP, g_part);
        cudaGetSymbolAddress((void**)&cAP, g_cA);
        cudaGetSymbolAddress((void**)&cBP, g_cB);
        cudaFuncSetAttribute(qkv_kernel, cudaFuncAttributeMaxDynamicSharedMemorySize, QKV_SMEM);
        cudaFuncSetAttribute(attn_kernel, cudaFuncAttributeMaxDynamicSharedMemorySize, ATTN_SMEM);
        cudaFuncSetAttribute(proj_kernel, cudaFuncAttributeMaxDynamicSharedMemorySize, PROJ_SMEM);
        init = true;
    }

    gn_part_k<<<256, 256>>>(x, partP);
    gn_fin_k<<<1, 512>>>(gs, gb, partP, cAP, cBP);
    qkv_kernel<<<dim3(32, BATCH), 256, QKV_SMEM>>>(x, cAP, cBP,
                                                   wq, bq, wk, bk, wv, bv,
                                                   qP, kP, vP);
    attn_kernel<<<dim3(32, BATCH), 256, ATTN_SMEM>>>(qP, kP, vP, oP);
    proj_kernel<<<dim3(32, BATCH), 256, PROJ_SMEM>>>(wp, bp, oP, x, out);
}